// round 1
// baseline (speedup 1.0000x reference)
#include <cuda_runtime.h>
#include <math.h>
#include <float.h>

// Problem constants (fixed by the dataset)
#define NN 100000
#define EE 1200000
#define RR 3

// ---------------- scratch (device globals; no allocation allowed) ----------
__device__ float  g_tfeat[NN * 64];          // tanh(2*d_feat)          25.6 MB
__device__ float4 g_hp[RR * NN * 16];        // hp per relation         76.8 MB
__device__ float4 g_p[RR * NN];              // per-node src-side logit part (+bias)
__device__ float4 g_q[RR * NN];              // per-node dst-side logit part
__device__ float  g_gs[RR * NN];             // t_feat . beta_es
__device__ float4 g_amax[RR * NN];           // segment max of alpha
__device__ float4 g_denom[RR * NN];          // segment sum of exp
__device__ float2 g_misc[RR * NN];           // {sum gs[s], cnt}
__device__ float4 g_accum[RR * NN * 16];     // sum(ex * hp[s])         76.8 MB
__device__ float  g_res[NN * 192];           // concat of per-relation results

// ---------------- helpers ---------------------------------------------------
__device__ __forceinline__ void atomicMaxF(float* a, float v) {
    if (v >= 0.f) atomicMax((int*)a, __float_as_int(v));
    else          atomicMin((unsigned int*)a, __float_as_uint(v));
}
__device__ __forceinline__ void redAdd4(float4* p, float4 v) {
    asm volatile("red.global.add.v4.f32 [%0], {%1,%2,%3,%4};"
                 :: "l"(p), "f"(v.x), "f"(v.y), "f"(v.z), "f"(v.w) : "memory");
}
__device__ __forceinline__ void redAdd2(float2* p, float2 v) {
    asm volatile("red.global.add.v2.f32 [%0], {%1,%2};"
                 :: "l"(p), "f"(v.x), "f"(v.y) : "memory");
}
__device__ __forceinline__ float lrelu(float x) { return x >= 0.f ? x : 0.01f * x; }

// ---------------- init ------------------------------------------------------
__global__ void k_init() {
    int i = blockIdx.x * blockDim.x + threadIdx.x;
    const float4 z4 = make_float4(0.f, 0.f, 0.f, 0.f);
    if (i < RR * NN * 16) g_accum[i] = z4;
    if (i < RR * NN) {
        g_denom[i] = z4;
        g_misc[i]  = make_float2(0.f, 0.f);
        g_amax[i]  = make_float4(-FLT_MAX, -FLT_MAX, -FLT_MAX, -FLT_MAX);
    }
}

// ---------------- prepA: d_feat->t_feat, hp0, p/q(r=0), gs(all r) ----------
__global__ __launch_bounds__(256) void k_prepA(
    const float* __restrict__ h, const float* __restrict__ d_w,
    const float* __restrict__ d_b, const float* __restrict__ w_w,
    const float* __restrict__ w_b, const float* __restrict__ atten_w,
    const float* __restrict__ atten_b, const float* __restrict__ beta)
{
    __shared__ float sW[8192];      // d_w | w_w[0]
    __shared__ float sH[4][64];
    __shared__ float sGS[4][2][4];
    int tx = threadIdx.x, ty = threadIdx.y;
    int tid = ty * 64 + tx;
    for (int i = tid; i < 4096; i += 256) sW[i] = d_w[i];
    for (int i = tid; i < 4096; i += 256) sW[4096 + i] = w_w[i];
    __syncthreads();

    int base = blockIdx.x * 32;
    for (int it = 0; it < 8; ++it) {
        int n = base + it * 4 + ty;
        sH[ty][tx] = h[n * 64 + tx];
        __syncthreads();
        float ad = 0.f, a0 = 0.f;
        #pragma unroll 16
        for (int k = 0; k < 64; ++k) {
            float hk = sH[ty][k];
            ad += hk * sW[k * 64 + tx];
            a0 += hk * sW[4096 + k * 64 + tx];
        }
        float t = tanhf(2.f * (ad + d_b[tx]));
        g_tfeat[n * 64 + tx] = t;
        float hp0 = a0 + w_b[tx];
        ((float*)g_hp)[(0 * NN + n) * 64 + tx] = hp0;

        int d = tx & 15;
        float ps = hp0 * atten_w[d] + t * atten_w[32 + d];
        float qs = hp0 * atten_w[16 + d];
        #pragma unroll
        for (int m = 8; m; m >>= 1) {
            ps += __shfl_xor_sync(0xffffffffu, ps, m, 16);
            qs += __shfl_xor_sync(0xffffffffu, qs, m, 16);
        }
        if (d == 0) {
            ((float*)&g_p[0 * NN + n])[tx >> 4] = ps + atten_b[0];
            ((float*)&g_q[0 * NN + n])[tx >> 4] = qs;
        }
        float v0 = t * beta[tx], v1 = t * beta[128 + tx], v2 = t * beta[256 + tx];
        #pragma unroll
        for (int m = 16; m; m >>= 1) {
            v0 += __shfl_xor_sync(0xffffffffu, v0, m);
            v1 += __shfl_xor_sync(0xffffffffu, v1, m);
            v2 += __shfl_xor_sync(0xffffffffu, v2, m);
        }
        if ((tx & 31) == 0) {
            int w = tx >> 5;
            sGS[ty][w][0] = v0; sGS[ty][w][1] = v1; sGS[ty][w][2] = v2;
        }
        __syncthreads();
        if (tx < 3) g_gs[tx * NN + n] = sGS[ty][0][tx] + sGS[ty][1][tx];
    }
}

// ---------------- prepB: hp1, hp2, p/q for r=1,2 ---------------------------
__global__ __launch_bounds__(256) void k_prepB(
    const float* __restrict__ h, const float* __restrict__ w_w,
    const float* __restrict__ w_b, const float* __restrict__ atten_w,
    const float* __restrict__ atten_b)
{
    __shared__ float sW[8192];      // w_w[1] | w_w[2]
    __shared__ float sH[4][64];
    int tx = threadIdx.x, ty = threadIdx.y;
    int tid = ty * 64 + tx;
    for (int i = tid; i < 8192; i += 256) sW[i] = w_w[4096 + i];
    __syncthreads();

    int base = blockIdx.x * 32;
    for (int it = 0; it < 8; ++it) {
        int n = base + it * 4 + ty;
        sH[ty][tx] = h[n * 64 + tx];
        __syncthreads();
        float a1 = 0.f, a2 = 0.f;
        #pragma unroll 16
        for (int k = 0; k < 64; ++k) {
            float hk = sH[ty][k];
            a1 += hk * sW[k * 64 + tx];
            a2 += hk * sW[4096 + k * 64 + tx];
        }
        float hp1 = a1 + w_b[64 + tx];
        float hp2 = a2 + w_b[128 + tx];
        ((float*)g_hp)[(1 * NN + n) * 64 + tx] = hp1;
        ((float*)g_hp)[(2 * NN + n) * 64 + tx] = hp2;
        float t = g_tfeat[n * 64 + tx];
        int d = tx & 15;
        #pragma unroll
        for (int r = 1; r < 3; ++r) {
            float hpv = (r == 1) ? hp1 : hp2;
            float ps = hpv * atten_w[r * 48 + d] + t * atten_w[r * 48 + 32 + d];
            float qs = hpv * atten_w[r * 48 + 16 + d];
            #pragma unroll
            for (int m = 8; m; m >>= 1) {
                ps += __shfl_xor_sync(0xffffffffu, ps, m, 16);
                qs += __shfl_xor_sync(0xffffffffu, qs, m, 16);
            }
            if (d == 0) {
                ((float*)&g_p[r * NN + n])[tx >> 4] = ps + atten_b[r];
                ((float*)&g_q[r * NN + n])[tx >> 4] = qs;
            }
        }
        __syncthreads();
    }
}

// ---------------- pass 1: per-edge leaky logits, segment max ----------------
__global__ __launch_bounds__(256) void k_max(
    const int* __restrict__ src, const int* __restrict__ dst)
{
    int r = blockIdx.y;
    int e = blockIdx.x * blockDim.x + threadIdx.x;
    if (e >= EE) return;
    int s = src[r * EE + e];
    int t = dst[r * EE + e];
    float4 lp = g_p[r * NN + s];
    float4 lq = g_q[r * NN + t];
    float a0 = lrelu(lp.x + lq.x), a1 = lrelu(lp.y + lq.y);
    float a2 = lrelu(lp.z + lq.z), a3 = lrelu(lp.w + lq.w);
    float* am = (float*)&g_amax[r * NN + t];
    atomicMaxF(am + 0, a0);
    atomicMaxF(am + 1, a1);
    atomicMaxF(am + 2, a2);
    atomicMaxF(am + 3, a3);
}

// ---------------- pass 2: scatter exp-weighted features (16 lanes/edge) -----
__global__ __launch_bounds__(256) void k_scatter(
    const int* __restrict__ src, const int* __restrict__ dst, int r)
{
    int gid = blockIdx.x * 256 + threadIdx.x;
    int e = gid >> 4;
    int l = gid & 15;
    if (e >= EE) return;
    int s = __ldg(src + r * EE + e);
    int t = __ldg(dst + r * EE + e);
    float4 lp = g_p[r * NN + s];
    float4 lq = g_q[r * NN + t];
    float4 am = g_amax[r * NN + t];
    float4 ex;
    ex.x = __expf(lrelu(lp.x + lq.x) - am.x);
    ex.y = __expf(lrelu(lp.y + lq.y) - am.y);
    ex.z = __expf(lrelu(lp.z + lq.z) - am.z);
    ex.w = __expf(lrelu(lp.w + lq.w) - am.w);
    float exh = (l < 8) ? (l < 4 ? ex.x : ex.y) : (l < 12 ? ex.z : ex.w);
    float4 v = g_hp[(r * NN + s) * 16 + l];
    redAdd4(&g_accum[(r * NN + t) * 16 + l],
            make_float4(v.x * exh, v.y * exh, v.z * exh, v.w * exh));
    if (l == 0) {
        redAdd4(&g_denom[r * NN + t], ex);
        redAdd2(&g_misc[r * NN + t], make_float2(g_gs[r * NN + s], 1.f));
    }
}

// ---------------- pass 3: per-node normalize, gate, residual ----------------
__global__ __launch_bounds__(256) void k_node(const float* __restrict__ beta)
{
    int n = (blockIdx.x * 256 + threadIdx.x) >> 5;
    int lane = threadIdx.x & 31;
    if (n >= NN) return;
    #pragma unroll
    for (int r = 0; r < RR; ++r) {
        float4 den = g_denom[r * NN + n];
        float2 mc  = g_misc[r * NN + n];
        float d0 = lane < 16 ? den.x : den.y;
        float d1 = lane < 16 ? den.z : den.w;
        const float* acc = (const float*)&g_accum[(r * NN + n) * 16];
        float o0 = acc[lane]      / fmaxf(d0, 1e-20f);
        float o1 = acc[lane + 32] / fmaxf(d1, 1e-20f);
        float dot = o0 * beta[r * 128 + 64 + lane] + o1 * beta[r * 128 + 96 + lane];
        #pragma unroll
        for (int m = 16; m; m >>= 1) dot += __shfl_xor_sync(0xffffffffu, dot, m);
        float ga = mc.x / fmaxf(mc.y, 1.f) + dot;
        float gate = 1.f / (1.f + __expf(-ga));
        const float* hp = (const float*)&g_hp[(r * NN + n) * 16];
        g_res[n * 192 + r * 64 + lane]      = gate * o0 + (1.f - gate) * hp[lane];
        g_res[n * 192 + r * 64 + lane + 32] = gate * o1 + (1.f - gate) * hp[lane + 32];
    }
}

// ---------------- pass 4: final [N,192]x[192,64] GEMM -----------------------
__global__ __launch_bounds__(256) void k_final(
    const float* __restrict__ lin_w, const float* __restrict__ lin_b,
    float* __restrict__ out)
{
    __shared__ float sW[96 * 64];   // 24 KB
    __shared__ float sX[32][96];    // 12 KB
    int tx = threadIdx.x, ty = threadIdx.y;
    int tid = ty * 64 + tx;
    int base = blockIdx.x * 32;
    float acc[8];
    float b = lin_b[tx];
    #pragma unroll
    for (int m = 0; m < 8; ++m) acc[m] = b;
    for (int c = 0; c < 2; ++c) {
        __syncthreads();
        for (int i = tid; i < 96 * 64; i += 256) sW[i] = lin_w[c * 96 * 64 + i];
        for (int i = tid; i < 32 * 96; i += 256) {
            int nn = i / 96, kk = i % 96;
            sX[nn][kk] = g_res[(base + nn) * 192 + c * 96 + kk];
        }
        __syncthreads();
        #pragma unroll
        for (int m = 0; m < 8; ++m) {
            int nn = m * 4 + ty;
            float a = acc[m];
            #pragma unroll 16
            for (int k = 0; k < 96; ++k) a += sX[nn][k] * sW[k * 64 + tx];
            acc[m] = a;
        }
    }
    #pragma unroll
    for (int m = 0; m < 8; ++m) out[(base + m * 4 + ty) * 64 + tx] = acc[m];
}

// ---------------- launch -----------------------------------------------------
extern "C" void kernel_launch(void* const* d_in, const int* in_sizes, int n_in,
                              void* d_out, int out_size)
{
    const float* h       = (const float*)d_in[0];
    const int*   src     = (const int*)  d_in[1];
    const int*   dst     = (const int*)  d_in[2];
    const float* d_w     = (const float*)d_in[3];
    const float* d_b     = (const float*)d_in[4];
    const float* w_w     = (const float*)d_in[5];
    const float* w_b     = (const float*)d_in[6];
    const float* atten_w = (const float*)d_in[7];
    const float* atten_b = (const float*)d_in[8];
    const float* beta    = (const float*)d_in[9];
    const float* lin_w   = (const float*)d_in[10];
    const float* lin_b   = (const float*)d_in[11];
    float* out = (float*)d_out;

    // init scratch (accum/denom/misc zero, amax = -FLT_MAX)
    k_init<<<(RR * NN * 16 + 255) / 256, 256>>>();

    dim3 blk(64, 4);
    k_prepA<<<NN / 32, blk>>>(h, d_w, d_b, w_w, w_b, atten_w, atten_b, beta);
    k_prepB<<<NN / 32, blk>>>(h, w_w, w_b, atten_w, atten_b);

    dim3 gmax((EE + 255) / 256, RR);
    k_max<<<gmax, 256>>>(src, dst);

    for (int r = 0; r < RR; ++r)
        k_scatter<<<(EE * 16) / 256, 256>>>(src, dst, r);

    k_node<<<(NN + 7) / 8, 256>>>(beta);

    k_final<<<NN / 32, blk>>>(lin_w, lin_b, out);
}

// round 2
// speedup vs baseline: 1.2676x; 1.2676x over previous
#include <cuda_runtime.h>
#include <math.h>
#include <float.h>

// Problem constants (fixed by the dataset)
#define NN 100000
#define EE 1200000
#define RR 3
#define M_TOT (RR * NN)
#define NBLK ((M_TOT + 1023) / 1024)

// ---------------- scratch (device globals; no allocation allowed) ----------
__device__ float  g_tfeat[NN * 64];          // tanh(2*d_feat)
__device__ float4 g_hp[RR * NN * 16];        // hp per relation (row-major 64f)
__device__ float4 g_p[RR * NN];              // per-node src-side logit part (+bias)
__device__ float4 g_q[RR * NN];              // per-node dst-side logit part
__device__ float  g_gs[RR * NN];             // t_feat . beta_es
__device__ float  g_res[NN * 192];           // concat of per-relation results
// CSR build
__device__ int    g_deg[M_TOT];
__device__ int    g_cur[M_TOT];
__device__ int    g_row[M_TOT];
__device__ int    g_bsum[512];
__device__ int    g_srt[RR * EE];            // src ids sorted by (r, dst)

__device__ __forceinline__ float lrelu(float x) { return x >= 0.f ? x : 0.01f * x; }

// ---------------- zero ------------------------------------------------------
__global__ void k_zero() {
    int i = blockIdx.x * blockDim.x + threadIdx.x;
    if (i < M_TOT) { g_deg[i] = 0; g_cur[i] = 0; }
}

// ---------------- prepA: d_feat->t_feat, hp0, p/q(r=0), gs(all r) ----------
__global__ __launch_bounds__(256) void k_prepA(
    const float* __restrict__ h, const float* __restrict__ d_w,
    const float* __restrict__ d_b, const float* __restrict__ w_w,
    const float* __restrict__ w_b, const float* __restrict__ atten_w,
    const float* __restrict__ atten_b, const float* __restrict__ beta)
{
    __shared__ float sW[8192];      // d_w | w_w[0]
    __shared__ float sH[4][64];
    __shared__ float sGS[4][2][4];
    int tx = threadIdx.x, ty = threadIdx.y;
    int tid = ty * 64 + tx;
    for (int i = tid; i < 4096; i += 256) sW[i] = d_w[i];
    for (int i = tid; i < 4096; i += 256) sW[4096 + i] = w_w[i];
    __syncthreads();

    int base = blockIdx.x * 32;
    for (int it = 0; it < 8; ++it) {
        int n = base + it * 4 + ty;
        sH[ty][tx] = h[n * 64 + tx];
        __syncthreads();
        float ad = 0.f, a0 = 0.f;
        #pragma unroll 16
        for (int k = 0; k < 64; ++k) {
            float hk = sH[ty][k];
            ad += hk * sW[k * 64 + tx];
            a0 += hk * sW[4096 + k * 64 + tx];
        }
        float t = tanhf(2.f * (ad + d_b[tx]));
        g_tfeat[n * 64 + tx] = t;
        float hp0 = a0 + w_b[tx];
        ((float*)g_hp)[(0 * NN + n) * 64 + tx] = hp0;

        int d = tx & 15;
        float ps = hp0 * atten_w[d] + t * atten_w[32 + d];
        float qs = hp0 * atten_w[16 + d];
        #pragma unroll
        for (int m = 8; m; m >>= 1) {
            ps += __shfl_xor_sync(0xffffffffu, ps, m, 16);
            qs += __shfl_xor_sync(0xffffffffu, qs, m, 16);
        }
        if (d == 0) {
            ((float*)&g_p[0 * NN + n])[tx >> 4] = ps + atten_b[0];
            ((float*)&g_q[0 * NN + n])[tx >> 4] = qs;
        }
        float v0 = t * beta[tx], v1 = t * beta[128 + tx], v2 = t * beta[256 + tx];
        #pragma unroll
        for (int m = 16; m; m >>= 1) {
            v0 += __shfl_xor_sync(0xffffffffu, v0, m);
            v1 += __shfl_xor_sync(0xffffffffu, v1, m);
            v2 += __shfl_xor_sync(0xffffffffu, v2, m);
        }
        if ((tx & 31) == 0) {
            int w = tx >> 5;
            sGS[ty][w][0] = v0; sGS[ty][w][1] = v1; sGS[ty][w][2] = v2;
        }
        __syncthreads();
        if (tx < 3) g_gs[tx * NN + n] = sGS[ty][0][tx] + sGS[ty][1][tx];
    }
}

// ---------------- prepB: hp1, hp2, p/q for r=1,2 ---------------------------
__global__ __launch_bounds__(256) void k_prepB(
    const float* __restrict__ h, const float* __restrict__ w_w,
    const float* __restrict__ w_b, const float* __restrict__ atten_w,
    const float* __restrict__ atten_b)
{
    __shared__ float sW[8192];      // w_w[1] | w_w[2]
    __shared__ float sH[4][64];
    int tx = threadIdx.x, ty = threadIdx.y;
    int tid = ty * 64 + tx;
    for (int i = tid; i < 8192; i += 256) sW[i] = w_w[4096 + i];
    __syncthreads();

    int base = blockIdx.x * 32;
    for (int it = 0; it < 8; ++it) {
        int n = base + it * 4 + ty;
        sH[ty][tx] = h[n * 64 + tx];
        __syncthreads();
        float a1 = 0.f, a2 = 0.f;
        #pragma unroll 16
        for (int k = 0; k < 64; ++k) {
            float hk = sH[ty][k];
            a1 += hk * sW[k * 64 + tx];
            a2 += hk * sW[4096 + k * 64 + tx];
        }
        float hp1 = a1 + w_b[64 + tx];
        float hp2 = a2 + w_b[128 + tx];
        ((float*)g_hp)[(1 * NN + n) * 64 + tx] = hp1;
        ((float*)g_hp)[(2 * NN + n) * 64 + tx] = hp2;
        float t = g_tfeat[n * 64 + tx];
        int d = tx & 15;
        #pragma unroll
        for (int r = 1; r < 3; ++r) {
            float hpv = (r == 1) ? hp1 : hp2;
            float ps = hpv * atten_w[r * 48 + d] + t * atten_w[r * 48 + 32 + d];
            float qs = hpv * atten_w[r * 48 + 16 + d];
            #pragma unroll
            for (int m = 8; m; m >>= 1) {
                ps += __shfl_xor_sync(0xffffffffu, ps, m, 16);
                qs += __shfl_xor_sync(0xffffffffu, qs, m, 16);
            }
            if (d == 0) {
                ((float*)&g_p[r * NN + n])[tx >> 4] = ps + atten_b[r];
                ((float*)&g_q[r * NN + n])[tx >> 4] = qs;
            }
        }
        __syncthreads();
    }
}

// ---------------- CSR: histogram, scan, build -------------------------------
__global__ void k_hist(const int* __restrict__ dst) {
    int e = blockIdx.x * blockDim.x + threadIdx.x;
    if (e >= RR * EE) return;
    int r = e / EE;
    atomicAdd(&g_deg[r * NN + dst[e]], 1);
}

__global__ __launch_bounds__(256) void k_scan1() {
    __shared__ int sS[256];
    int b = blockIdx.x;
    int base = b * 1024 + threadIdx.x * 4;
    int v[4]; int s = 0;
    #pragma unroll
    for (int j = 0; j < 4; ++j) {
        v[j] = (base + j < M_TOT) ? g_deg[base + j] : 0;
        s += v[j];
    }
    sS[threadIdx.x] = s;
    __syncthreads();
    for (int off = 1; off < 256; off <<= 1) {
        int t = (threadIdx.x >= off) ? sS[threadIdx.x - off] : 0;
        __syncthreads();
        sS[threadIdx.x] += t;
        __syncthreads();
    }
    int run = sS[threadIdx.x] - s;
    #pragma unroll
    for (int j = 0; j < 4; ++j) {
        if (base + j < M_TOT) g_row[base + j] = run;
        run += v[j];
    }
    if (threadIdx.x == 255) g_bsum[b] = sS[255];
}

__global__ __launch_bounds__(512) void k_scan2() {
    __shared__ int sS[512];
    int i = threadIdx.x;
    int v = (i < NBLK) ? g_bsum[i] : 0;
    sS[i] = v;
    __syncthreads();
    for (int off = 1; off < 512; off <<= 1) {
        int t = (i >= off) ? sS[i - off] : 0;
        __syncthreads();
        sS[i] += t;
        __syncthreads();
    }
    if (i < NBLK) g_bsum[i] = sS[i] - v;  // exclusive
}

__global__ void k_scan3() {
    int i = blockIdx.x * blockDim.x + threadIdx.x;
    if (i < M_TOT) g_row[i] += g_bsum[i >> 10];
}

__global__ void k_build(const int* __restrict__ src, const int* __restrict__ dst) {
    int e = blockIdx.x * blockDim.x + threadIdx.x;
    if (e >= RR * EE) return;
    int r = e / EE;
    int idx = r * NN + dst[e];
    int pos = g_row[idx] + atomicAdd(&g_cur[idx], 1);
    g_srt[pos] = src[e];
}

// ---------------- aggregate: warp per (node, relation), pull-style ----------
__global__ __launch_bounds__(256) void k_aggr(const float* __restrict__ beta)
{
    const unsigned FULL = 0xffffffffu;
    int warp = threadIdx.x >> 5;
    int lane = threadIdx.x & 31;
    int n = blockIdx.x * 8 + warp;
    int r = blockIdx.y;
    if (n >= NN) return;
    int idx = r * NN + n;
    int start = g_row[idx];
    int deg   = g_deg[idx];

    // per-lane head for exp phase: head = lane & 3, edge-in-chunk = lane >> 2
    float qc = __ldg((const float*)g_q + idx * 4 + (lane & 3));

    float2 acc = make_float2(0.f, 0.f);   // output dims 2*lane, 2*lane+1
    float denacc = 0.f;                    // partial denom for head lane&3
    float gsacc = 0.f;

    int nchunk = (deg + 7) >> 3;
    const float* pbase = (const float*)g_p + (size_t)r * NN * 4;
    const float* hpbase = (const float*)g_hp + (size_t)r * NN * 64;
    for (int c = 0; c < nchunk; ++c) {
        int eo = c * 8 + (lane >> 2);
        bool val = eo < deg;
        int s_l = val ? g_srt[start + eo] : 0;
        float pl = __ldg(pbase + s_l * 4 + (lane & 3));
        float ex = val ? __expf(lrelu(pl + qc)) : 0.f;
        denacc += ex;
        if (val && (lane & 3) == 0) gsacc += g_gs[idx - n + s_l];  // g_gs[r*NN + s]
        int lim = deg - c * 8;
        if (lim > 8) lim = 8;
        #pragma unroll
        for (int j = 0; j < 8; ++j) {
            if (j >= lim) break;                         // warp-uniform
            int   sj = __shfl_sync(FULL, s_l, 4 * j);
            float e  = __shfl_sync(FULL, ex, 4 * j + (lane >> 3));
            const float2* hpw = (const float2*)(hpbase + (size_t)sj * 64);
            float2 v = __ldg(hpw + lane);
            acc.x += e * v.x;
            acc.y += e * v.y;
        }
    }
    // reduce denom across lanes with same head (lane&3)
    #pragma unroll
    for (int m = 4; m < 32; m <<= 1) denacc += __shfl_xor_sync(FULL, denacc, m);
    float d = __shfl_sync(FULL, denacc, lane >> 3);       // head for dims 2l,2l+1
    float o0 = acc.x / fmaxf(d, 1e-20f);
    float o1 = acc.y / fmaxf(d, 1e-20f);
    // gs total
    #pragma unroll
    for (int m = 4; m < 32; m <<= 1) gsacc += __shfl_xor_sync(FULL, gsacc, m);
    float gstot = __shfl_sync(FULL, gsacc, 0);
    // gate dot: beta row r, out part at offset 64
    const float2* bet = (const float2*)(beta + r * 128 + 64);
    float2 b2 = __ldg(bet + lane);
    float dot = o0 * b2.x + o1 * b2.y;
    #pragma unroll
    for (int m = 16; m; m >>= 1) dot += __shfl_xor_sync(FULL, dot, m);
    float ga = gstot / fmaxf((float)deg, 1.f) + dot;
    float gate = 1.f / (1.f + __expf(-ga));
    // residual with hp, write result
    const float2* hpn = (const float2*)(hpbase + (size_t)n * 64);
    float2 hpv = __ldg(hpn + lane);
    float2* res = (float2*)(g_res + n * 192 + r * 64);
    res[lane] = make_float2(gate * o0 + (1.f - gate) * hpv.x,
                            gate * o1 + (1.f - gate) * hpv.y);
}

// ---------------- final [N,192]x[192,64] GEMM --------------------------------
__global__ __launch_bounds__(256) void k_final(
    const float* __restrict__ lin_w, const float* __restrict__ lin_b,
    float* __restrict__ out)
{
    __shared__ float sW[96 * 64];   // 24 KB
    __shared__ float sX[32][96];    // 12 KB
    int tx = threadIdx.x, ty = threadIdx.y;
    int tid = ty * 64 + tx;
    int base = blockIdx.x * 32;
    float acc[8];
    float b = lin_b[tx];
    #pragma unroll
    for (int m = 0; m < 8; ++m) acc[m] = b;
    for (int c = 0; c < 2; ++c) {
        __syncthreads();
        for (int i = tid; i < 96 * 64; i += 256) sW[i] = lin_w[c * 96 * 64 + i];
        for (int i = tid; i < 32 * 96; i += 256) {
            int nn = i / 96, kk = i % 96;
            sX[nn][kk] = g_res[(base + nn) * 192 + c * 96 + kk];
        }
        __syncthreads();
        #pragma unroll
        for (int m = 0; m < 8; ++m) {
            int nn = m * 4 + ty;
            float a = acc[m];
            #pragma unroll 16
            for (int k = 0; k < 96; ++k) a += sX[nn][k] * sW[k * 64 + tx];
            acc[m] = a;
        }
    }
    #pragma unroll
    for (int m = 0; m < 8; ++m) out[(base + m * 4 + ty) * 64 + tx] = acc[m];
}

// ---------------- launch -----------------------------------------------------
extern "C" void kernel_launch(void* const* d_in, const int* in_sizes, int n_in,
                              void* d_out, int out_size)
{
    const float* h       = (const float*)d_in[0];
    const int*   src     = (const int*)  d_in[1];
    const int*   dst     = (const int*)  d_in[2];
    const float* d_w     = (const float*)d_in[3];
    const float* d_b     = (const float*)d_in[4];
    const float* w_w     = (const float*)d_in[5];
    const float* w_b     = (const float*)d_in[6];
    const float* atten_w = (const float*)d_in[7];
    const float* atten_b = (const float*)d_in[8];
    const float* beta    = (const float*)d_in[9];
    const float* lin_w   = (const float*)d_in[10];
    const float* lin_b   = (const float*)d_in[11];
    float* out = (float*)d_out;

    k_zero<<<(M_TOT + 255) / 256, 256>>>();

    dim3 blk(64, 4);
    k_prepA<<<NN / 32, blk>>>(h, d_w, d_b, w_w, w_b, atten_w, atten_b, beta);
    k_prepB<<<NN / 32, blk>>>(h, w_w, w_b, atten_w, atten_b);

    k_hist<<<(RR * EE + 255) / 256, 256>>>(dst);
    k_scan1<<<NBLK, 256>>>();
    k_scan2<<<1, 512>>>();
    k_scan3<<<(M_TOT + 255) / 256, 256>>>();
    k_build<<<(RR * EE + 255) / 256, 256>>>(src, dst);

    dim3 gaggr((NN + 7) / 8, RR);
    k_aggr<<<gaggr, 256>>>(beta);

    k_final<<<NN / 32, blk>>>(lin_w, lin_b, out);
}